// round 14
// baseline (speedup 1.0000x reference)
#include <cuda_runtime.h>
#include <cuda_bf16.h>
#include <cuda_fp16.h>
#include <cstdint>

#define NNODES 50000
#define DEG 16
#define FDIM 128
#define NCTA 391                 // ceil(50000/128)

// ---------------------------------------------------------------------------
// Scratch (device globals: allocation-free per harness rules)
// ---------------------------------------------------------------------------
__device__ __align__(16) float  g_A[NNODES * FDIM];     // fp32 (read per-node)
__device__ __align__(16) __half g_Bh[NNODES * FDIM];    // fp16 (gathered per-edge)
__device__ __align__(16) __half g_xh[NNODES * FDIM];    // fp16 x copy (gathered per-edge)
__device__ __align__(16) __half g_supH[NNODES * FDIM];  // fp16 (gathered per-edge)

// bf16 hi/lo word-interleaved images: per row 128 words.
__device__ __align__(16) uint32_t g_xnimg[NCTA * 128 * 128];
__device__ __align__(16) uint32_t g_wmimg[256 * 128];   // fused: rows<128 Wm_top, >=128 Wm_bot ([n][k])
__device__ __align__(16) uint32_t g_wsimg[128 * 128];   // weight ([n][k])

// ---------------------------------------------------------------------------
// helpers
// ---------------------------------------------------------------------------
__device__ __forceinline__ uint32_t sa(const void* p)
{
    return (uint32_t)__cvta_generic_to_shared(p);
}

__device__ __forceinline__ void cp16(uint32_t dst, const void* src)
{
    asm volatile("cp.async.cg.shared.global [%0], [%1], 16;\n" ::"r"(dst), "l"(src));
}

__device__ __forceinline__ void cp_commit()
{
    asm volatile("cp.async.commit_group;\n");
}

__device__ __forceinline__ void cp_wait_all()
{
    asm volatile("cp.async.wait_group 0;\n" ::: "memory");
}

__device__ __forceinline__ void mma_bf16(float c[4], uint32_t a0, uint32_t a1,
                                         uint32_t a2, uint32_t a3,
                                         uint32_t b0, uint32_t b1)
{
    asm volatile(
        "mma.sync.aligned.m16n8k16.row.col.f32.bf16.bf16.f32 "
        "{%0,%1,%2,%3}, {%4,%5,%6,%7}, {%8,%9}, {%0,%1,%2,%3};\n"
        : "+f"(c[0]), "+f"(c[1]), "+f"(c[2]), "+f"(c[3])
        : "r"(a0), "r"(a1), "r"(a2), "r"(a3), "r"(b0), "r"(b1));
}

// bf16 hi/lo split of two consecutive elements -> (hi word, lo word)
__device__ __forceinline__ void split2(float v0, float v1, uint32_t& wh,
                                       uint32_t& wl)
{
    __nv_bfloat16 h0 = __float2bfloat16(v0);
    __nv_bfloat16 h1 = __float2bfloat16(v1);
    __nv_bfloat16 l0 = __float2bfloat16(v0 - __bfloat162float(h0));
    __nv_bfloat16 l1 = __float2bfloat16(v1 - __bfloat162float(h1));
    wh = (uint32_t)__bfloat16_as_ushort(h0) |
         ((uint32_t)__bfloat16_as_ushort(h1) << 16);
    wl = (uint32_t)__bfloat16_as_ushort(l0) |
         ((uint32_t)__bfloat16_as_ushort(l1) << 16);
}

// 4 consecutive elements -> uint4 image block (hi01, lo01, hi23, lo23)
__device__ __forceinline__ uint4 img4(float4 v)
{
    uint4 r;
    split2(v.x, v.y, r.x, r.y);
    split2(v.z, v.w, r.z, r.w);
    return r;
}

// sigmoid via MUFU.TANH: sigma(z) = 0.5*tanh(z/2) + 0.5   (1 MUFU op)
__device__ __forceinline__ float sigf(float z)
{
    float t;
    asm("tanh.approx.f32 %0, %1;" : "=f"(t) : "f"(z * 0.5f));
    return fmaf(t, 0.5f, 0.5f);
}

// ---------------------------------------------------------------------------
// presplit_w: build W images ([n row][k word] layout for mma ".col" B operand)
// ---------------------------------------------------------------------------
__global__ void presplit_w(const float* __restrict__ wmask,
                           const float* __restrict__ weight)
{
    int i = blockIdx.x * 256 + threadIdx.x;
    if (i < 16384) {                          // Wm: 256 n x 64 word-pairs
        int n = i >> 6, wk = i & 63, k = wk * 2;
        const float* src = (n < 128) ? (wmask + n)
                                     : (wmask + 128 * 128 + (n - 128));
        uint32_t wh, wl;
        split2(src[k * 128], src[(k + 1) * 128], wh, wl);
        g_wmimg[n * 128 + 2 * wk]     = wh;
        g_wmimg[n * 128 + 2 * wk + 1] = wl;
    } else if (i < 24576) {                   // Ws: 128 n x 64 word-pairs
        int j = i - 16384;
        int n = j >> 6, wk = j & 63, k = wk * 2;
        uint32_t wh, wl;
        split2(weight[k * 128 + n], weight[(k + 1) * 128 + n], wh, wl);
        g_wsimg[n * 128 + 2 * wk]     = wh;
        g_wsimg[n * 128 + 2 * wk + 1] = wl;
    }
}

// ---------------------------------------------------------------------------
// 3xBF16 GEMM: C[128-row tile, 128] = X . W^T(image [n][k]).
// 256 threads, warp tile m32 x n64. K-chunk 32, double-buffered.
// SPLITX: A operand loaded as raw fp32, hi/lo-split in regs -> STS; the
//         blockIdx.y==0 CTAs also emit a COALESCED fp16 copy of x to g_xh.
// H0/H1: output dtype of C0/C1 (fp16 when the array is gathered per-edge).
// blockIdx.y selects W half / output (fused A|B GEMM).
// ---------------------------------------------------------------------------
template <bool SPLITX, bool H0, bool H1>
__global__ __launch_bounds__(256, 2) void gemm_bf3(
    const float* __restrict__ Xf, const uint32_t* __restrict__ Ximg,
    const uint32_t* __restrict__ Wimg,
    void* __restrict__ C0, void* __restrict__ C1, int nrows)
{
    extern __shared__ uint32_t sm[];
    const int TILE = 128 * 40;                // 5120 words per operand tile

    const int tid  = threadIdx.x;
    const int lane = tid & 31;
    const int warp = tid >> 5;
    const int g    = lane >> 2;
    const int tq   = lane & 3;
    const int wm   = warp & 3;                // rows wm*32
    const int wn   = warp >> 2;               // cols wn*64
    const int rowBase = blockIdx.x * 128;

    const uint32_t* Wbase = Wimg + (size_t)blockIdx.y * (128 * 128);

    float acc[2][8][4];
#pragma unroll
    for (int mt = 0; mt < 2; ++mt)
#pragma unroll
        for (int nt = 0; nt < 8; ++nt)
#pragma unroll
            for (int i = 0; i < 4; ++i) acc[mt][nt][i] = 0.f;

    auto stage = [&](int p, int c) {
        uint32_t* As = sm + p * 2 * TILE;
        uint32_t* Bs = As + TILE;
#pragma unroll
        for (int i = 0; i < 4; ++i) {         // A: 1024 16B units
            int idx = tid + i * 256;
            int r = idx >> 3, u = idx & 7;
            if (SPLITX) {
                int gr = rowBase + r;
                float4 v = make_float4(0.f, 0.f, 0.f, 0.f);
                if (gr < nrows) {
                    v = *(const float4*)(Xf + (size_t)gr * 128 + c * 32 + u * 4);
                    if (blockIdx.y == 0) {
                        // coalesced fp16 copy of x: 8B at unit (c*8+u)
                        __half2 h01 = __floats2half2_rn(v.x, v.y);
                        __half2 h23 = __floats2half2_rn(v.z, v.w);
                        *(uint2*)((__half*)g_xh + (size_t)gr * 128 + c * 32 + u * 4) =
                            make_uint2(*(uint32_t*)&h01, *(uint32_t*)&h23);
                    }
                }
                *(uint4*)(As + r * 40 + u * 4) = img4(v);
            } else {
                cp16(sa(As + r * 40 + u * 4),
                     Ximg + (size_t)(rowBase + r) * 128 + c * 32 + u * 4);
            }
        }
#pragma unroll
        for (int i = 0; i < 4; ++i) {         // B: 1024 16B units
            int idx = tid + i * 256;
            int r = idx >> 3, u = idx & 7;
            cp16(sa(Bs + r * 40 + u * 4),
                 Wbase + (size_t)r * 128 + c * 32 + u * 4);
        }
    };

    stage(0, 0);
    cp_commit();
    cp_wait_all();
    __syncthreads();

    int p = 0;
    for (int c = 0; c < 4; ++c) {
        if (c < 3) {
            stage(1 - p, c + 1);
            cp_commit();
        }

        const uint32_t* As = sm + p * 2 * TILE;
        const uint32_t* Bs = As + TILE;
#pragma unroll
        for (int kb = 0; kb < 2; ++kb) {      // two k16 halves of the chunk
            const int w0 = 2 * (kb * 8 + tq);
            uint32_t ah[2][4], al[2][4];
#pragma unroll
            for (int mt = 0; mt < 2; ++mt) {
                int r0 = wm * 32 + mt * 16 + g;
                uint2 p0 = *(const uint2*)(As + r0 * 40 + w0);
                uint2 p1 = *(const uint2*)(As + (r0 + 8) * 40 + w0);
                uint2 p2 = *(const uint2*)(As + r0 * 40 + w0 + 8);
                uint2 p3 = *(const uint2*)(As + (r0 + 8) * 40 + w0 + 8);
                ah[mt][0] = p0.x; al[mt][0] = p0.y;
                ah[mt][1] = p1.x; al[mt][1] = p1.y;
                ah[mt][2] = p2.x; al[mt][2] = p2.y;
                ah[mt][3] = p3.x; al[mt][3] = p3.y;
            }
#pragma unroll
            for (int nt = 0; nt < 8; ++nt) {
                int n = wn * 64 + nt * 8 + g;
                uint2 q0 = *(const uint2*)(Bs + n * 40 + w0);
                uint2 q1 = *(const uint2*)(Bs + n * 40 + w0 + 8);
                uint32_t bh0 = q0.x, bl0 = q0.y, bh1 = q1.x, bl1 = q1.y;
#pragma unroll
                for (int mt = 0; mt < 2; ++mt) {
                    mma_bf16(acc[mt][nt], ah[mt][0], ah[mt][1], ah[mt][2],
                             ah[mt][3], bh0, bh1);                      // hi*hi
                    mma_bf16(acc[mt][nt], ah[mt][0], ah[mt][1], ah[mt][2],
                             ah[mt][3], bl0, bl1);                      // hi*lo
                    mma_bf16(acc[mt][nt], al[mt][0], al[mt][1], al[mt][2],
                             al[mt][3], bh0, bh1);                      // lo*hi
                }
            }
        }

        if (c < 3) {
            cp_wait_all();
            __syncthreads();
            p ^= 1;
        }
    }

    // Epilogue: fp32 or fp16 per output array (all coalesced)
    void* C = blockIdx.y ? C1 : C0;
    const bool asHalf = blockIdx.y ? H1 : H0;
#pragma unroll
    for (int mt = 0; mt < 2; ++mt) {
        int r0 = rowBase + wm * 32 + mt * 16 + g;
#pragma unroll
        for (int nt = 0; nt < 8; ++nt) {
            int n = wn * 64 + nt * 8 + 2 * tq;
            if (asHalf) {
                __half* Ch = (__half*)C;
                if (r0 < nrows)
                    *(__half2*)(Ch + (size_t)r0 * FDIM + n) =
                        __floats2half2_rn(acc[mt][nt][0], acc[mt][nt][1]);
                if (r0 + 8 < nrows)
                    *(__half2*)(Ch + (size_t)(r0 + 8) * FDIM + n) =
                        __floats2half2_rn(acc[mt][nt][2], acc[mt][nt][3]);
            } else {
                float* Cf = (float*)C;
                if (r0 < nrows)
                    *(float2*)(Cf + (size_t)r0 * FDIM + n) =
                        make_float2(acc[mt][nt][0], acc[mt][nt][1]);
                if (r0 + 8 < nrows)
                    *(float2*)(Cf + (size_t)(r0 + 8) * FDIM + n) =
                        make_float2(acc[mt][nt][2], acc[mt][nt][3]);
            }
        }
    }
}

// ---------------------------------------------------------------------------
// x_new[i] = x[i] + sum_e sigmoid(A[i] + B[src_e]) * x[src_e]
// Per edge-lane: two 8B gathers (B fp16, x fp16) = 16B total.
// Output written in image format for the S GEMM.
// ---------------------------------------------------------------------------
__global__ __launch_bounds__(256) void edge_mask_kernel(
    const float* __restrict__ x, const int* __restrict__ edge_src)
{
    int node = blockIdx.x * 8 + (threadIdx.x >> 5);
    if (node >= NNODES) return;
    int lane = threadIdx.x & 31;

    const float4* x4 = (const float4*)x;
    const float4* A4 = (const float4*)g_A;
    const uint2*  B2 = (const uint2*)g_Bh;    // 8B = 4 halves per lane
    const uint2*  X2 = (const uint2*)g_xh;    // 8B = 4 halves per lane

    float4 a = A4[node * 32 + lane];
    float4 acc = make_float4(0.f, 0.f, 0.f, 0.f);
    int ebase = node * DEG;
#pragma unroll
    for (int e = 0; e < DEG; ++e) {
        int src = __ldg(edge_src + ebase + e);
        uint2 braw = __ldg(&B2[src * 32 + lane]);
        uint2 xraw = __ldg(&X2[src * 32 + lane]);
        float2 b01 = __half22float2(*(const __half2*)&braw.x);
        float2 b23 = __half22float2(*(const __half2*)&braw.y);
        float2 x01 = __half22float2(*(const __half2*)&xraw.x);
        float2 x23 = __half22float2(*(const __half2*)&xraw.y);
        acc.x = fmaf(sigf(a.x + b01.x), x01.x, acc.x);
        acc.y = fmaf(sigf(a.y + b01.y), x01.y, acc.y);
        acc.z = fmaf(sigf(a.z + b23.x), x23.x, acc.z);
        acc.w = fmaf(sigf(a.w + b23.y), x23.y, acc.w);
    }
    float4 xs = x4[node * 32 + lane];
    float4 v = make_float4(xs.x + acc.x, xs.y + acc.y,
                           xs.z + acc.z, xs.w + acc.w);
    ((uint4*)g_xnimg)[node * 32 + lane] = img4(v);
}

// ---------------------------------------------------------------------------
// out[i] = bias + sum_e adj[e] * support[src_e]   (support gathered in fp16)
// ---------------------------------------------------------------------------
__global__ __launch_bounds__(256) void out_kernel(
    const float* __restrict__ adj_vals, const int* __restrict__ edge_src,
    const float* __restrict__ bias, float* __restrict__ out)
{
    int node = blockIdx.x * 8 + (threadIdx.x >> 5);
    if (node >= NNODES) return;
    int lane = threadIdx.x & 31;

    const uint2* S2 = (const uint2*)g_supH;   // 8B = 4 halves per lane
    float4 acc = ((const float4*)bias)[lane];
    int ebase = node * DEG;
#pragma unroll
    for (int e = 0; e < DEG; ++e) {
        int src  = __ldg(edge_src + ebase + e);
        float av = __ldg(adj_vals + ebase + e);
        uint2 sraw = __ldg(&S2[src * 32 + lane]);
        float2 s01 = __half22float2(*(const __half2*)&sraw.x);
        float2 s23 = __half22float2(*(const __half2*)&sraw.y);
        acc.x = fmaf(av, s01.x, acc.x);
        acc.y = fmaf(av, s01.y, acc.y);
        acc.z = fmaf(av, s23.x, acc.z);
        acc.w = fmaf(av, s23.y, acc.w);
    }
    ((float4*)out)[node * 32 + lane] = acc;
}

extern "C" void kernel_launch(void* const* d_in, const int* in_sizes, int n_in,
                              void* d_out, int out_size)
{
    const float* x      = (const float*)d_in[0];
    const float* weight = (const float*)d_in[1];
    const float* bias   = (const float*)d_in[2];
    const float* wmask  = (const float*)d_in[3];  // [256,128] row-major
    const float* adj    = (const float*)d_in[4];
    const int*   esrc   = (const int*)d_in[5];
    float* out = (float*)d_out;

    float* A;
    __half *Bh, *supH;
    uint32_t *xni, *wmi, *wsi;
    cudaGetSymbolAddress((void**)&A, g_A);
    cudaGetSymbolAddress((void**)&Bh, g_Bh);
    cudaGetSymbolAddress((void**)&supH, g_supH);
    cudaGetSymbolAddress((void**)&xni, g_xnimg);
    cudaGetSymbolAddress((void**)&wmi, g_wmimg);
    cudaGetSymbolAddress((void**)&wsi, g_wsimg);

    const int smemB = 4 * 128 * 40 * 4;            // 81920
    cudaFuncSetAttribute((const void*)gemm_bf3<true, false, true>,
                         cudaFuncAttributeMaxDynamicSharedMemorySize, smemB);
    cudaFuncSetAttribute((const void*)gemm_bf3<false, true, true>,
                         cudaFuncAttributeMaxDynamicSharedMemorySize, smemB);

    const int egrid = (NNODES + 7) / 8;            // 6250

    // 0) W images (bf16 hi/lo word-interleaved)
    presplit_w<<<96, 256>>>(wmask, weight);
    // 1) A = x @ Wm_top (fp32), B = x @ Wm_bot (fp16)  [fused via blockIdx.y];
    //    y==0 CTAs also emit coalesced fp16 x copy to g_xh during staging.
    gemm_bf3<true, false, true><<<dim3(NCTA, 2), 256, smemB>>>(
        x, nullptr, wmi, A, Bh, NNODES);
    // 2) x_new = x + seg_sum(sigmoid(A[dst]+B[src]) * x[src]) -> image
    edge_mask_kernel<<<egrid, 256>>>(x, esrc);
    // 3) support = x_new @ weight  (fp16 output)
    gemm_bf3<false, true, true><<<dim3(NCTA, 1), 256, smemB>>>(
        nullptr, xni, wsi, supH, nullptr, NNODES);
    // 4) out = seg_sum(adj * support[src]) + bias
    out_kernel<<<egrid, 256>>>(adj, esrc, bias, out);
}

// round 16
// speedup vs baseline: 1.0775x; 1.0775x over previous
#include <cuda_runtime.h>
#include <cuda_bf16.h>
#include <cuda_fp16.h>
#include <cstdint>

#define NNODES 50000
#define DEG 16
#define FDIM 128
#define NCTA64 782               // ceil(50000/64)
#define NCTA 391                 // ceil(50000/128)

// ---------------------------------------------------------------------------
// Scratch (device globals: allocation-free per harness rules)
// ---------------------------------------------------------------------------
__device__ __align__(16) float  g_A[NNODES * FDIM];     // fp32 (read per-node)
__device__ __align__(16) __half g_Bh[NNODES * FDIM];    // fp16 (gathered per-edge)
__device__ __align__(16) __half g_supH[NNODES * FDIM];  // fp16 (gathered per-edge)

// bf16 hi/lo word-interleaved images: per row 128 words.
__device__ __align__(16) uint32_t g_xnimg[NCTA * 128 * 128];
__device__ __align__(16) uint32_t g_wmimg[256 * 128];   // fused: rows<128 Wm_top, >=128 Wm_bot ([n][k])
__device__ __align__(16) uint32_t g_wsimg[128 * 128];   // weight ([n][k])

// ---------------------------------------------------------------------------
// helpers
// ---------------------------------------------------------------------------
__device__ __forceinline__ uint32_t sa(const void* p)
{
    return (uint32_t)__cvta_generic_to_shared(p);
}

__device__ __forceinline__ void cp16(uint32_t dst, const void* src)
{
    asm volatile("cp.async.cg.shared.global [%0], [%1], 16;\n" ::"r"(dst), "l"(src));
}

__device__ __forceinline__ void cp_commit()
{
    asm volatile("cp.async.commit_group;\n");
}

__device__ __forceinline__ void cp_wait_all()
{
    asm volatile("cp.async.wait_group 0;\n" ::: "memory");
}

__device__ __forceinline__ void mma_bf16(float c[4], uint32_t a0, uint32_t a1,
                                         uint32_t a2, uint32_t a3,
                                         uint32_t b0, uint32_t b1)
{
    asm volatile(
        "mma.sync.aligned.m16n8k16.row.col.f32.bf16.bf16.f32 "
        "{%0,%1,%2,%3}, {%4,%5,%6,%7}, {%8,%9}, {%0,%1,%2,%3};\n"
        : "+f"(c[0]), "+f"(c[1]), "+f"(c[2]), "+f"(c[3])
        : "r"(a0), "r"(a1), "r"(a2), "r"(a3), "r"(b0), "r"(b1));
}

// bf16 hi/lo split of two consecutive elements -> (hi word, lo word)
__device__ __forceinline__ void split2(float v0, float v1, uint32_t& wh,
                                       uint32_t& wl)
{
    __nv_bfloat16 h0 = __float2bfloat16(v0);
    __nv_bfloat16 h1 = __float2bfloat16(v1);
    __nv_bfloat16 l0 = __float2bfloat16(v0 - __bfloat162float(h0));
    __nv_bfloat16 l1 = __float2bfloat16(v1 - __bfloat162float(h1));
    wh = (uint32_t)__bfloat16_as_ushort(h0) |
         ((uint32_t)__bfloat16_as_ushort(h1) << 16);
    wl = (uint32_t)__bfloat16_as_ushort(l0) |
         ((uint32_t)__bfloat16_as_ushort(l1) << 16);
}

// 4 consecutive elements -> uint4 image block (hi01, lo01, hi23, lo23)
__device__ __forceinline__ uint4 img4(float4 v)
{
    uint4 r;
    split2(v.x, v.y, r.x, r.y);
    split2(v.z, v.w, r.z, r.w);
    return r;
}

// sigmoid via MUFU.TANH: sigma(z) = 0.5*tanh(z/2) + 0.5   (1 MUFU op)
__device__ __forceinline__ float sigf(float z)
{
    float t;
    asm("tanh.approx.f32 %0, %1;" : "=f"(t) : "f"(z * 0.5f));
    return fmaf(t, 0.5f, 0.5f);
}

// ---------------------------------------------------------------------------
// presplit_w: build W images ([n row][k word] layout for mma ".col" B operand)
// ---------------------------------------------------------------------------
__global__ void presplit_w(const float* __restrict__ wmask,
                           const float* __restrict__ weight)
{
    int i = blockIdx.x * 256 + threadIdx.x;
    if (i < 16384) {                          // Wm: 256 n x 64 word-pairs
        int n = i >> 6, wk = i & 63, k = wk * 2;
        const float* src = (n < 128) ? (wmask + n)
                                     : (wmask + 128 * 128 + (n - 128));
        uint32_t wh, wl;
        split2(src[k * 128], src[(k + 1) * 128], wh, wl);
        g_wmimg[n * 128 + 2 * wk]     = wh;
        g_wmimg[n * 128 + 2 * wk + 1] = wl;
    } else if (i < 24576) {                   // Ws: 128 n x 64 word-pairs
        int j = i - 16384;
        int n = j >> 6, wk = j & 63, k = wk * 2;
        uint32_t wh, wl;
        split2(weight[k * 128 + n], weight[(k + 1) * 128 + n], wh, wl);
        g_wsimg[n * 128 + 2 * wk]     = wh;
        g_wsimg[n * 128 + 2 * wk + 1] = wl;
    }
}

// ---------------------------------------------------------------------------
// 3xBF16 GEMM: C[64-row tile, 128] = X . W^T(image [n][k]).
// 256 threads = 8 warps of m32 x n32 (2x4 frags, 32 acc regs) -> 3 CTAs/SM.
// K-chunk 32, double-buffered. Smem row stride 40 words.
// SPLITX: A operand loaded as raw fp32 and hi/lo-split in registers -> STS.
// H0/H1: output dtype of C0/C1. blockIdx.y selects W half (fused A|B GEMM).
// ---------------------------------------------------------------------------
template <bool SPLITX, bool H0, bool H1>
__global__ __launch_bounds__(256, 3) void gemm_bf3(
    const float* __restrict__ Xf, const uint32_t* __restrict__ Ximg,
    const uint32_t* __restrict__ Wimg,
    void* __restrict__ C0, void* __restrict__ C1, int nrows)
{
    extern __shared__ uint32_t sm[];
    const int TA   = 64 * 40;                 // 2560 words: A tile
    const int TB   = 128 * 40;                // 5120 words: B tile
    const int TBUF = TA + TB;                 // 7680 words per buffer

    const int tid  = threadIdx.x;
    const int lane = tid & 31;
    const int warp = tid >> 5;
    const int g    = lane >> 2;
    const int tq   = lane & 3;
    const int wm   = warp & 1;                // rows wm*32
    const int wn   = warp >> 1;               // cols wn*32
    const int rowBase = blockIdx.x * 64;

    const uint32_t* Wbase = Wimg + (size_t)blockIdx.y * (128 * 128);

    float acc[2][4][4];
#pragma unroll
    for (int mt = 0; mt < 2; ++mt)
#pragma unroll
        for (int nt = 0; nt < 4; ++nt)
#pragma unroll
            for (int i = 0; i < 4; ++i) acc[mt][nt][i] = 0.f;

    auto stage = [&](int p, int c) {
        uint32_t* As = sm + p * TBUF;
        uint32_t* Bs = As + TA;
#pragma unroll
        for (int i = 0; i < 2; ++i) {         // A: 512 16B units
            int idx = tid + i * 256;
            int r = idx >> 3, u = idx & 7;
            if (SPLITX) {
                int gr = rowBase + r;
                float4 v = (gr < nrows)
                    ? *(const float4*)(Xf + (size_t)gr * 128 + c * 32 + u * 4)
                    : make_float4(0.f, 0.f, 0.f, 0.f);
                *(uint4*)(As + r * 40 + u * 4) = img4(v);
            } else {
                cp16(sa(As + r * 40 + u * 4),
                     Ximg + (size_t)(rowBase + r) * 128 + c * 32 + u * 4);
            }
        }
#pragma unroll
        for (int i = 0; i < 4; ++i) {         // B: 1024 16B units
            int idx = tid + i * 256;
            int r = idx >> 3, u = idx & 7;
            cp16(sa(Bs + r * 40 + u * 4),
                 Wbase + (size_t)r * 128 + c * 32 + u * 4);
        }
    };

    stage(0, 0);
    cp_commit();
    cp_wait_all();
    __syncthreads();

    int p = 0;
    for (int c = 0; c < 4; ++c) {
        if (c < 3) {
            stage(1 - p, c + 1);
            cp_commit();
        }

        const uint32_t* As = sm + p * TBUF;
        const uint32_t* Bs = As + TA;
#pragma unroll
        for (int kb = 0; kb < 2; ++kb) {      // two k16 halves of the chunk
            const int w0 = 2 * (kb * 8 + tq);
            uint32_t ah[2][4], al[2][4];
#pragma unroll
            for (int mt = 0; mt < 2; ++mt) {
                int r0 = wm * 32 + mt * 16 + g;
                uint2 p0 = *(const uint2*)(As + r0 * 40 + w0);
                uint2 p1 = *(const uint2*)(As + (r0 + 8) * 40 + w0);
                uint2 p2 = *(const uint2*)(As + r0 * 40 + w0 + 8);
                uint2 p3 = *(const uint2*)(As + (r0 + 8) * 40 + w0 + 8);
                ah[mt][0] = p0.x; al[mt][0] = p0.y;
                ah[mt][1] = p1.x; al[mt][1] = p1.y;
                ah[mt][2] = p2.x; al[mt][2] = p2.y;
                ah[mt][3] = p3.x; al[mt][3] = p3.y;
            }
#pragma unroll
            for (int nt = 0; nt < 4; ++nt) {
                int n = wn * 32 + nt * 8 + g;
                uint2 q0 = *(const uint2*)(Bs + n * 40 + w0);
                uint2 q1 = *(const uint2*)(Bs + n * 40 + w0 + 8);
                uint32_t bh0 = q0.x, bl0 = q0.y, bh1 = q1.x, bl1 = q1.y;
#pragma unroll
                for (int mt = 0; mt < 2; ++mt) {
                    mma_bf16(acc[mt][nt], ah[mt][0], ah[mt][1], ah[mt][2],
                             ah[mt][3], bh0, bh1);                      // hi*hi
                    mma_bf16(acc[mt][nt], ah[mt][0], ah[mt][1], ah[mt][2],
                             ah[mt][3], bl0, bl1);                      // hi*lo
                    mma_bf16(acc[mt][nt], al[mt][0], al[mt][1], al[mt][2],
                             al[mt][3], bh0, bh1);                      // lo*hi
                }
            }
        }

        if (c < 3) {
            cp_wait_all();
            __syncthreads();
            p ^= 1;
        }
    }

    // Epilogue: fp32 or fp16 per output array (all coalesced)
    void* C = blockIdx.y ? C1 : C0;
    const bool asHalf = blockIdx.y ? H1 : H0;
#pragma unroll
    for (int mt = 0; mt < 2; ++mt) {
        int r0 = rowBase + wm * 32 + mt * 16 + g;
#pragma unroll
        for (int nt = 0; nt < 4; ++nt) {
            int n = wn * 32 + nt * 8 + 2 * tq;
            if (asHalf) {
                __half* Ch = (__half*)C;
                if (r0 < nrows)
                    *(__half2*)(Ch + (size_t)r0 * FDIM + n) =
                        __floats2half2_rn(acc[mt][nt][0], acc[mt][nt][1]);
                if (r0 + 8 < nrows)
                    *(__half2*)(Ch + (size_t)(r0 + 8) * FDIM + n) =
                        __floats2half2_rn(acc[mt][nt][2], acc[mt][nt][3]);
            } else {
                float* Cf = (float*)C;
                if (r0 < nrows)
                    *(float2*)(Cf + (size_t)r0 * FDIM + n) =
                        make_float2(acc[mt][nt][0], acc[mt][nt][1]);
                if (r0 + 8 < nrows)
                    *(float2*)(Cf + (size_t)(r0 + 8) * FDIM + n) =
                        make_float2(acc[mt][nt][2], acc[mt][nt][3]);
            }
        }
    }
}

// ---------------------------------------------------------------------------
// x_new[i] = x[i] + sum_e sigmoid(A[i] + B[src_e]) * x[src_e]
// B gathered in fp16. Output written in image format for the S GEMM.
// ---------------------------------------------------------------------------
__global__ __launch_bounds__(256) void edge_mask_kernel(
    const float* __restrict__ x, const int* __restrict__ edge_src)
{
    int node = blockIdx.x * 8 + (threadIdx.x >> 5);
    if (node >= NNODES) return;
    int lane = threadIdx.x & 31;

    const float4* x4 = (const float4*)x;
    const float4* A4 = (const float4*)g_A;
    const uint2*  B2 = (const uint2*)g_Bh;    // 8B = 4 halves per lane

    float4 a = A4[node * 32 + lane];
    float4 acc = make_float4(0.f, 0.f, 0.f, 0.f);
    int ebase = node * DEG;
#pragma unroll
    for (int e = 0; e < DEG; ++e) {
        int src = __ldg(edge_src + ebase + e);
        uint2 braw = __ldg(&B2[src * 32 + lane]);
        float2 b01 = __half22float2(*(const __half2*)&braw.x);
        float2 b23 = __half22float2(*(const __half2*)&braw.y);
        float4 xv = x4[src * 32 + lane];
        acc.x = fmaf(sigf(a.x + b01.x), xv.x, acc.x);
        acc.y = fmaf(sigf(a.y + b01.y), xv.y, acc.y);
        acc.z = fmaf(sigf(a.z + b23.x), xv.z, acc.z);
        acc.w = fmaf(sigf(a.w + b23.y), xv.w, acc.w);
    }
    float4 xs = x4[node * 32 + lane];
    float4 v = make_float4(xs.x + acc.x, xs.y + acc.y,
                           xs.z + acc.z, xs.w + acc.w);
    ((uint4*)g_xnimg)[node * 32 + lane] = img4(v);
}

// ---------------------------------------------------------------------------
// out[i] = bias + sum_e adj[e] * support[src_e]   (support gathered in fp16)
// ---------------------------------------------------------------------------
__global__ __launch_bounds__(256) void out_kernel(
    const float* __restrict__ adj_vals, const int* __restrict__ edge_src,
    const float* __restrict__ bias, float* __restrict__ out)
{
    int node = blockIdx.x * 8 + (threadIdx.x >> 5);
    if (node >= NNODES) return;
    int lane = threadIdx.x & 31;

    const uint2* S2 = (const uint2*)g_supH;   // 8B = 4 halves per lane
    float4 acc = ((const float4*)bias)[lane];
    int ebase = node * DEG;
#pragma unroll
    for (int e = 0; e < DEG; ++e) {
        int src  = __ldg(edge_src + ebase + e);
        float av = __ldg(adj_vals + ebase + e);
        uint2 sraw = __ldg(&S2[src * 32 + lane]);
        float2 s01 = __half22float2(*(const __half2*)&sraw.x);
        float2 s23 = __half22float2(*(const __half2*)&sraw.y);
        acc.x = fmaf(av, s01.x, acc.x);
        acc.y = fmaf(av, s01.y, acc.y);
        acc.z = fmaf(av, s23.x, acc.z);
        acc.w = fmaf(av, s23.y, acc.w);
    }
    ((float4*)out)[node * 32 + lane] = acc;
}

extern "C" void kernel_launch(void* const* d_in, const int* in_sizes, int n_in,
                              void* d_out, int out_size)
{
    const float* x      = (const float*)d_in[0];
    const float* weight = (const float*)d_in[1];
    const float* bias   = (const float*)d_in[2];
    const float* wmask  = (const float*)d_in[3];  // [256,128] row-major
    const float* adj    = (const float*)d_in[4];
    const int*   esrc   = (const int*)d_in[5];
    float* out = (float*)d_out;

    float* A;
    __half *Bh, *supH;
    uint32_t *xni, *wmi, *wsi;
    cudaGetSymbolAddress((void**)&A, g_A);
    cudaGetSymbolAddress((void**)&Bh, g_Bh);
    cudaGetSymbolAddress((void**)&supH, g_supH);
    cudaGetSymbolAddress((void**)&xni, g_xnimg);
    cudaGetSymbolAddress((void**)&wmi, g_wmimg);
    cudaGetSymbolAddress((void**)&wsi, g_wsimg);

    const int smemB = 2 * (64 + 128) * 40 * 4;     // 61440
    cudaFuncSetAttribute((const void*)gemm_bf3<true, false, true>,
                         cudaFuncAttributeMaxDynamicSharedMemorySize, smemB);
    cudaFuncSetAttribute((const void*)gemm_bf3<false, true, true>,
                         cudaFuncAttributeMaxDynamicSharedMemorySize, smemB);

    const int egrid = (NNODES + 7) / 8;            // 6250

    // 0) W images (bf16 hi/lo word-interleaved)
    presplit_w<<<96, 256>>>(wmask, weight);
    // 1) A = x @ Wm_top (fp32), B = x @ Wm_bot (fp16)  [fused via blockIdx.y]
    gemm_bf3<true, false, true><<<dim3(NCTA64, 2), 256, smemB>>>(
        x, nullptr, wmi, A, Bh, NNODES);
    // 2) x_new = x + seg_sum(sigmoid(A[dst]+B[src]) * x[src]) -> image
    edge_mask_kernel<<<egrid, 256>>>(x, esrc);
    // 3) support = x_new @ weight  (fp16 output)
    gemm_bf3<false, true, true><<<dim3(NCTA64, 1), 256, smemB>>>(
        nullptr, xni, wsi, supH, nullptr, NNODES);
    // 4) out = seg_sum(adj * support[src]) + bias
    out_kernel<<<egrid, 256>>>(adj, esrc, bias, out);
}